// round 3
// baseline (speedup 1.0000x reference)
#include <cuda_runtime.h>
#include <cstdint>

#define BATCH   32
#define NPRED   8400
#define NCLS    80
#define ROWF    85
#define KPRE    512
#define MAXOUT  100
#define CONF_TH 0.25f
#define IOU_TH  0.45f
#define CLS_OFF 4096.0f

// Scratch (no allocations allowed -> device globals)
__device__ unsigned long long g_keys[BATCH * NPRED];
__device__ unsigned int       g_bmax[BATCH];
__device__ unsigned long long g_topk[BATCH * KPRE];

// ---------------------------------------------------------------------------
// K0: zero per-batch max accumulators
// ---------------------------------------------------------------------------
__global__ void k_init() {
    if (threadIdx.x < BATCH) g_bmax[threadIdx.x] = 0u;
}

// ---------------------------------------------------------------------------
// K1: per-row score = obj * max(cls); key = (score_bits<<32) | ~n  (unique!)
// one warp per prediction row (coalesced 85-float row read)
// ---------------------------------------------------------------------------
__global__ void k_score(const float* __restrict__ pred) {
    int warp = threadIdx.x >> 5, lane = threadIdx.x & 31;
    int b = blockIdx.y;
    int n = blockIdx.x * 8 + warp;
    const float* row = pred + ((size_t)b * NPRED + n) * ROWF;

    float best = -1.f;
#pragma unroll
    for (int i = 0; i < 3; i++) {
        int c = lane + i * 32;
        float v = (c < NCLS) ? row[5 + c] : -1.f;
        best = fmaxf(best, v);
    }
#pragma unroll
    for (int off = 16; off; off >>= 1)
        best = fmaxf(best, __shfl_xor_sync(0xFFFFFFFFu, best, off));

    __shared__ unsigned int smax;
    if (threadIdx.x == 0) smax = 0u;
    __syncthreads();

    if (lane == 0) {
        float obj = row[4];
        float score = obj * best;                 // >= 0
        unsigned sb = __float_as_uint(score);     // positive-float bit order == int order
        g_keys[(size_t)b * NPRED + n] =
            ((unsigned long long)sb << 32) | (unsigned)(~(unsigned)n);
        atomicMax(&smax, sb);
    }
    __syncthreads();
    if (threadIdx.x == 0) atomicMax(&g_bmax[b], smax);
}

// ---------------------------------------------------------------------------
// K2: per-batch exact top-512 (radix-select on unique 64-bit keys) + bitonic
// sort descending. One block (512 threads) per batch; keys staged in smem.
// ---------------------------------------------------------------------------
__global__ void k_select() {
    extern __shared__ unsigned long long s_keys[];   // NPRED + KPRE entries
    unsigned long long* topsm = s_keys + NPRED;

    __shared__ unsigned int        hist[256];
    __shared__ unsigned long long  sh_prefix;
    __shared__ int                 sh_remaining;
    __shared__ unsigned int        cnt;

    int b = blockIdx.x;
    int tid = threadIdx.x;   // 512 threads

    float conf = fminf(CONF_TH, __uint_as_float(g_bmax[b]));
    unsigned confb = __float_as_uint(conf);

    // load keys, masking invalid (score < conf) -> score field 0 (acts as -inf,
    // index tiebreak preserved so -inf entries come out ascending-index)
    for (int i = tid; i < NPRED; i += 512) {
        unsigned long long k = g_keys[(size_t)b * NPRED + i];
        if ((unsigned)(k >> 32) < confb) k &= 0xFFFFFFFFull;
        s_keys[i] = k;
    }
    if (tid == 0) { sh_prefix = 0ull; sh_remaining = KPRE; }
    __syncthreads();

    // 8x 8-bit radix select: find exact KPRE-th largest key
    for (int p = 7; p >= 0; p--) {
        if (tid < 256) hist[tid] = 0u;
        __syncthreads();
        unsigned long long pref = sh_prefix;
        for (int i = tid; i < NPRED; i += 512) {
            unsigned long long k = s_keys[i];
            bool match = (p == 7) || ((k >> ((p + 1) * 8)) == pref);
            if (match) atomicAdd(&hist[(unsigned)(k >> (p * 8)) & 0xFFu], 1u);
        }
        __syncthreads();
        if (tid == 0) {
            int rem = sh_remaining;
            int cum = 0;
            for (int bb = 255; bb >= 0; bb--) {
                cum += (int)hist[bb];
                if (cum >= rem) {
                    sh_remaining = rem - (cum - (int)hist[bb]);
                    sh_prefix = (pref << 8) | (unsigned)bb;
                    break;
                }
            }
        }
        __syncthreads();
    }

    unsigned long long pivot = sh_prefix;   // exact 512th-largest key
    if (tid == 0) cnt = 0u;
    __syncthreads();

    // compact: keys unique -> exactly KPRE keys >= pivot
    for (int i = tid; i < NPRED; i += 512) {
        unsigned long long k = s_keys[i];
        if (k >= pivot) {
            unsigned pos = atomicAdd(&cnt, 1u);
            topsm[pos] = k;
        }
    }
    __syncthreads();

    // bitonic sort descending (512 elems, 512 threads)
    for (int kk = 2; kk <= KPRE; kk <<= 1) {
        for (int j = kk >> 1; j > 0; j >>= 1) {
            int ixj = tid ^ j;
            if (ixj > tid) {
                bool up = ((tid & kk) == 0);
                unsigned long long a = topsm[tid], c = topsm[ixj];
                bool sw = up ? (a < c) : (a > c);
                if (sw) { topsm[tid] = c; topsm[ixj] = a; }
            }
            __syncthreads();
        }
    }

    for (int i = tid; i < KPRE; i += 512)
        g_topk[(size_t)b * KPRE + i] = topsm[i];
}

// ---------------------------------------------------------------------------
// K3: per-batch gather + class-offset boxes + 512x512 IoU bitmask + greedy
// NMS + emit top-100 dets & mask. One block (256 threads) per batch.
// ---------------------------------------------------------------------------
__global__ void k_nms(const float* __restrict__ pred, float* __restrict__ out,
                      int out_size) {
    extern __shared__ float sm[];
    float*    sx1   = sm;               // 512
    float*    sy1   = sm + 512;
    float*    sx2   = sm + 1024;
    float*    sy2   = sm + 1536;
    float*    sar   = sm + 2048;        // areas
    float*    sdet  = sm + 2560;        // 512 * 7
    unsigned* ssup  = (unsigned*)(sdet + 512 * 7);   // 512 * 16 words
    unsigned* skeep = ssup + 512 * 16;  // 16
    unsigned* svld  = skeep + 16;       // 16
    unsigned* swpre = svld + 16;        // 17

    int b = blockIdx.x;
    int tid = threadIdx.x;              // 256
    int warp = tid >> 5, lane = tid & 31;

    if (tid < 16) { skeep[tid] = 0u; svld[tid] = 0u; }
    __syncthreads();

    // gather: one warp per selected entry
    for (int e = warp; e < KPRE; e += 8) {
        unsigned long long key = g_topk[(size_t)b * KPRE + e];
        unsigned sb = (unsigned)(key >> 32);
        int n = (int)(~(unsigned)key);
        const float* row = pred + ((size_t)b * NPRED + n) * ROWF;

        float bv = -1.f; int bi = 0;
#pragma unroll
        for (int i = 0; i < 3; i++) {
            int c = lane + i * 32;
            if (c < NCLS) {
                float v = row[5 + c];
                if (v > bv) { bv = v; bi = c; }   // first-max within lane
            }
        }
#pragma unroll
        for (int off = 16; off; off >>= 1) {
            float ov = __shfl_xor_sync(0xFFFFFFFFu, bv, off);
            int   oi = __shfl_xor_sync(0xFFFFFFFFu, bi, off);
            if (ov > bv || (ov == bv && oi < bi)) { bv = ov; bi = oi; }
        }
        if (lane == 0) {
            float cx = row[0], cy = row[1], w = row[2], h = row[3], obj = row[4];
            float x1 = cx - 0.5f * w, y1 = cy - 0.5f * h;
            float x2 = cx + 0.5f * w, y2 = cy + 0.5f * h;
            float off = (float)bi * CLS_OFF;
            sx1[e] = x1 + off; sy1[e] = y1 + off;
            sx2[e] = x2 + off; sy2[e] = y2 + off;
            sar[e] = (x2 - x1) * (y2 - y1);
            float* d = sdet + e * 7;
            d[0] = x1; d[1] = y1; d[2] = x2; d[3] = y2;
            d[4] = obj; d[5] = bv; d[6] = (float)bi;
            if (sb != 0u) atomicOr(&svld[e >> 5], 1u << (e & 31));
        }
    }
    __syncthreads();

    // suppression bitmask: sup[i] bit j  <=>  iou(i,j) > thresh
    for (int i = tid; i < KPRE; i += 256) {
        float ax1 = sx1[i], ay1 = sy1[i], ax2 = sx2[i], ay2 = sy2[i], aa = sar[i];
        for (int wd = 0; wd < 16; wd++) {
            unsigned bits = 0u;
#pragma unroll 4
            for (int t = 0; t < 32; t++) {
                int j = wd * 32 + t;
                float ix1 = fmaxf(ax1, sx1[j]);
                float iy1 = fmaxf(ay1, sy1[j]);
                float ix2 = fminf(ax2, sx2[j]);
                float iy2 = fminf(ay2, sy2[j]);
                float iw = fmaxf(ix2 - ix1, 0.f);
                float ih = fmaxf(iy2 - iy1, 0.f);
                float inter = iw * ih;
                float uni = aa + sar[j] - inter;
                float iou = inter / (uni + 1e-9f);
                if (iou > IOU_TH) bits |= (1u << t);
            }
            ssup[i * 16 + wd] = bits;
        }
    }
    __syncthreads();

    // sequential greedy NMS (warp 0): keep[i] = valid[i] && !any(keep & sup[i])
    if (warp == 0) {
        for (int i = 0; i < KPRE; i++) {
            unsigned wv = 0u;
            if (lane < 16) wv = skeep[lane] & ssup[i * 16 + lane];
            bool suppressed = __any_sync(0xFFFFFFFFu, wv != 0u);
            if (lane == 0) {
                bool val = (svld[i >> 5] >> (i & 31)) & 1u;
                if (val && !suppressed) skeep[i >> 5] |= 1u << (i & 31);
            }
            __syncwarp();
        }
        if (lane == 0) {
            unsigned c = 0;
            for (int wd = 0; wd < 16; wd++) { swpre[wd] = c; c += __popc(skeep[wd]); }
            swpre[16] = c;
        }
    }
    __syncthreads();

    // emit: kept entries ascending -> rows [0, nkeep); remaining rows zeroed
    float* dets = out + (size_t)b * MAXOUT * 7;
    bool has_mask = (out_size >= BATCH * MAXOUT * 7 + BATCH * MAXOUT);
    float* mask = out + (size_t)BATCH * MAXOUT * 7 + (size_t)b * MAXOUT;

    for (int i = tid; i < KPRE; i += 256) {
        if ((skeep[i >> 5] >> (i & 31)) & 1u) {
            unsigned r = swpre[i >> 5] +
                         __popc(skeep[i >> 5] & ((1u << (i & 31)) - 1u));
            if (r < MAXOUT) {
                float* d = sdet + i * 7;
                float* o = dets + (size_t)r * 7;
#pragma unroll
                for (int c = 0; c < 7; c++) o[c] = d[c];
                if (has_mask) mask[r] = 1.0f;
            }
        }
    }
    unsigned nk = swpre[16];
    int start = (nk < (unsigned)MAXOUT) ? (int)nk : MAXOUT;
    for (int r = start + tid; r < MAXOUT; r += 256) {
        float* o = dets + (size_t)r * 7;
#pragma unroll
        for (int c = 0; c < 7; c++) o[c] = 0.f;
        if (has_mask) mask[r] = 0.f;
    }
}

// ---------------------------------------------------------------------------
extern "C" void kernel_launch(void* const* d_in, const int* in_sizes, int n_in,
                              void* d_out, int out_size) {
    (void)in_sizes; (void)n_in;
    const float* pred = (const float*)d_in[0];
    float* out = (float*)d_out;

    static_assert(NPRED % 8 == 0, "rows per block");

    cudaFuncSetAttribute(k_select, cudaFuncAttributeMaxDynamicSharedMemorySize,
                         (NPRED + KPRE) * 8);
    cudaFuncSetAttribute(k_nms, cudaFuncAttributeMaxDynamicSharedMemorySize,
                         (2560 + 512 * 7) * 4 + 512 * 16 * 4 + (16 + 16 + 17) * 4);

    k_init<<<1, 32>>>();
    dim3 g1(NPRED / 8, BATCH);
    k_score<<<g1, 256>>>(pred);
    k_select<<<BATCH, 512, (NPRED + KPRE) * 8>>>();
    k_nms<<<BATCH, 256,
            (2560 + 512 * 7) * 4 + 512 * 16 * 4 + (16 + 16 + 17) * 4>>>(
        pred, out, out_size);
}

// round 8
// speedup vs baseline: 1.9210x; 1.9210x over previous
#include <cuda_runtime.h>
#include <cstdint>

#define BATCH   32
#define NPRED   8400
#define NCLS    80
#define ROWF    85
#define KPRE    512
#define MAXOUT  100
#define CONF_TH 0.25f
#define IOU_TH  0.45f
#define CLS_OFF 4096.0f
#define FULLM   0xFFFFFFFFu

// Scratch (no allocations allowed -> device globals)
__device__ unsigned long long g_keys[BATCH * NPRED];
__device__ unsigned int       g_bmax[BATCH];
__device__ unsigned long long g_topk[BATCH * KPRE];
__device__ float              g_box[5 * BATCH * KPRE];   // SoA: x1,y1,x2,y2,area (class-offset applied)
__device__ float              g_det[BATCH * KPRE * 7];   // x1,y1,x2,y2,obj,conf,cls
__device__ unsigned int       g_valid[BATCH * 16];
__device__ unsigned int       g_sup[BATCH * KPRE * 16];  // 1 MB suppression bitmask

// ---------------------------------------------------------------------------
// K0: zero per-batch max accumulators + valid bitmasks
// ---------------------------------------------------------------------------
__global__ void k_init() {
    int tid = threadIdx.x;
    if (tid < BATCH) g_bmax[tid] = 0u;
    if (tid < BATCH * 16) g_valid[tid] = 0u;
}

// ---------------------------------------------------------------------------
// K1: per-row score = obj * max(cls); key = (score_bits<<32) | ~n  (unique)
// one warp per prediction row (coalesced 85-float row read)
// ---------------------------------------------------------------------------
__global__ void k_score(const float* __restrict__ pred) {
    int warp = threadIdx.x >> 5, lane = threadIdx.x & 31;
    int b = blockIdx.y;
    int n = blockIdx.x * 8 + warp;
    const float* row = pred + ((size_t)b * NPRED + n) * ROWF;

    float best = -1.f;
#pragma unroll
    for (int i = 0; i < 3; i++) {
        int c = lane + i * 32;
        float v = (c < NCLS) ? row[5 + c] : -1.f;
        best = fmaxf(best, v);
    }
#pragma unroll
    for (int off = 16; off; off >>= 1)
        best = fmaxf(best, __shfl_xor_sync(FULLM, best, off));

    __shared__ unsigned int smax;
    if (threadIdx.x == 0) smax = 0u;
    __syncthreads();

    if (lane == 0) {
        float obj = row[4];
        float score = obj * best;                 // >= 0
        unsigned sb = __float_as_uint(score);     // positive-float bit order == int order
        g_keys[(size_t)b * NPRED + n] =
            ((unsigned long long)sb << 32) | (unsigned)(~(unsigned)n);
        atomicMax(&smax, sb);
    }
    __syncthreads();
    if (threadIdx.x == 0) atomicMax(&g_bmax[b], smax);
}

// ---------------------------------------------------------------------------
// K2: per-batch exact top-512 (radix-select on unique 64-bit keys) + bitonic
// sort descending. One block (1024 threads) per batch; keys staged in smem.
// ---------------------------------------------------------------------------
__global__ void k_select() {
    extern __shared__ unsigned long long s_keys[];   // NPRED + KPRE entries
    unsigned long long* topsm = s_keys + NPRED;

    __shared__ unsigned int        hist[256];
    __shared__ unsigned long long  sh_prefix;
    __shared__ int                 sh_remaining;
    __shared__ unsigned int        cnt;

    int b = blockIdx.x;
    int tid = threadIdx.x;   // 1024 threads
    const int NITER = (NPRED + 1023) / 1024;   // uniform trip count (9)

    float conf = fminf(CONF_TH, __uint_as_float(g_bmax[b]));
    unsigned confb = __float_as_uint(conf);

    // load keys, masking invalid (score < conf) -> score field 0
    for (int i = tid; i < NPRED; i += 1024) {
        unsigned long long k = g_keys[(size_t)b * NPRED + i];
        if ((unsigned)(k >> 32) < confb) k &= 0xFFFFFFFFull;
        s_keys[i] = k;
    }
    if (tid == 0) { sh_prefix = 0ull; sh_remaining = KPRE; }
    __syncthreads();

    // 8x 8-bit radix select: find exact KPRE-th largest key
    for (int p = 7; p >= 0; p--) {
        if (tid < 256) hist[tid] = 0u;
        __syncthreads();
        unsigned long long pref = sh_prefix;
        // UNIFORM trip count: every lane executes __match_any_sync every
        // iteration (sentinel bucket 0x100 for inactive / non-matching lanes).
        for (int it = 0; it < NITER; it++) {
            int i = it * 1024 + tid;
            unsigned bucket = 0x100u;
            if (i < NPRED) {
                unsigned long long k = s_keys[i];
                bool match = (p == 7) || ((k >> ((p + 1) * 8)) == pref);
                if (match) bucket = (unsigned)(k >> (p * 8)) & 0xFFu;
            }
            unsigned peers = __match_any_sync(FULLM, bucket);
            if (bucket != 0x100u && ((__ffs(peers) - 1) == (tid & 31)))
                atomicAdd(&hist[bucket], __popc(peers));
        }
        __syncthreads();
        if (tid < 32) {
            int lane = tid;
            int rem = sh_remaining;
            // lane handles bins [lane*8, lane*8+8)
            unsigned s = 0;
#pragma unroll
            for (int q = 0; q < 8; q++) s += hist[(lane << 3) + q];
            // inclusive suffix sum across lanes: S_l = sum_{m>=l} s_m
            unsigned S = s;
#pragma unroll
            for (int off = 1; off < 32; off <<= 1) {
                unsigned v = __shfl_down_sync(FULLM, S, off);
                if (lane + off < 32) S += v;
            }
            unsigned bal = __ballot_sync(FULLM, (int)S >= rem);
            int L = 31 - __clz(bal);      // highest lane group reaching rem
            if (lane == L) {
                int cum = (int)(S - s);   // suffix excluding this group
                for (int bb = (L << 3) + 7; bb >= (L << 3); bb--) {
                    cum += (int)hist[bb];
                    if (cum >= rem) {
                        sh_remaining = rem - (cum - (int)hist[bb]);
                        sh_prefix = (pref << 8) | (unsigned)bb;
                        break;
                    }
                }
            }
        }
        __syncthreads();
    }

    unsigned long long pivot = sh_prefix;   // exact 512th-largest key
    if (tid == 0) cnt = 0u;
    __syncthreads();

    // compact: keys unique -> exactly KPRE keys >= pivot
    for (int i = tid; i < NPRED; i += 1024) {
        unsigned long long k = s_keys[i];
        if (k >= pivot) {
            unsigned pos = atomicAdd(&cnt, 1u);
            topsm[pos] = k;
        }
    }
    __syncthreads();

    // bitonic sort descending (512 elems, first 512 threads)
    for (int kk = 2; kk <= KPRE; kk <<= 1) {
        for (int j = kk >> 1; j > 0; j >>= 1) {
            if (tid < KPRE) {
                int ixj = tid ^ j;
                if (ixj > tid) {
                    bool up = ((tid & kk) == 0);
                    unsigned long long a = topsm[tid], c = topsm[ixj];
                    bool sw = up ? (a < c) : (a > c);
                    if (sw) { topsm[tid] = c; topsm[ixj] = a; }
                }
            }
            __syncthreads();
        }
    }

    for (int i = tid; i < KPRE; i += 1024)
        g_topk[(size_t)b * KPRE + i] = topsm[i];
}

// ---------------------------------------------------------------------------
// K3: gather selected rows -> boxes (class-offset) + dets + valid bits.
// Grid (64, BATCH) x 256 threads, one warp per entry: latency fully hidden.
// ---------------------------------------------------------------------------
__global__ void k_gather(const float* __restrict__ pred) {
    int warp = threadIdx.x >> 5, lane = threadIdx.x & 31;
    int b = blockIdx.y;
    int e = blockIdx.x * 8 + warp;

    unsigned long long key = g_topk[(size_t)b * KPRE + e];
    unsigned sb = (unsigned)(key >> 32);
    int n = (int)(~(unsigned)key);
    const float* row = pred + ((size_t)b * NPRED + n) * ROWF;

    float bv = -1.f; int bi = 0;
#pragma unroll
    for (int i = 0; i < 3; i++) {
        int c = lane + i * 32;
        if (c < NCLS) {
            float v = row[5 + c];
            if (v > bv) { bv = v; bi = c; }
        }
    }
#pragma unroll
    for (int off = 16; off; off >>= 1) {
        float ov = __shfl_xor_sync(FULLM, bv, off);
        int   oi = __shfl_xor_sync(FULLM, bi, off);
        if (ov > bv || (ov == bv && oi < bi)) { bv = ov; bi = oi; }
    }
    if (lane == 0) {
        float cx = row[0], cy = row[1], w = row[2], h = row[3], obj = row[4];
        float x1 = cx - 0.5f * w, y1 = cy - 0.5f * h;
        float x2 = cx + 0.5f * w, y2 = cy + 0.5f * h;
        float off = (float)bi * CLS_OFF;
        int base = b * KPRE + e;
        g_box[0 * BATCH * KPRE + base] = x1 + off;
        g_box[1 * BATCH * KPRE + base] = y1 + off;
        g_box[2 * BATCH * KPRE + base] = x2 + off;
        g_box[3 * BATCH * KPRE + base] = y2 + off;
        g_box[4 * BATCH * KPRE + base] = (x2 - x1) * (y2 - y1);
        float* d = g_det + (size_t)base * 7;
        d[0] = x1; d[1] = y1; d[2] = x2; d[3] = y2;
        d[4] = obj; d[5] = bv; d[6] = (float)bi;
        if (sb != 0u) atomicOr(&g_valid[b * 16 + (e >> 5)], 1u << (e & 31));
    }
}

// ---------------------------------------------------------------------------
// K4: suppression bitmask sup[i] bit j <=> iou(i,j) > thresh.
// Grid (4, BATCH) x 128 threads: one row per thread, 128 rows per block.
// ---------------------------------------------------------------------------
__global__ void k_iou() {
    __shared__ float sx1[KPRE], sy1[KPRE], sx2[KPRE], sy2[KPRE], sar[KPRE];
    int b = blockIdx.y;
    int tid = threadIdx.x;   // 128

    for (int i = tid; i < KPRE; i += 128) {
        int base = b * KPRE + i;
        sx1[i] = g_box[0 * BATCH * KPRE + base];
        sy1[i] = g_box[1 * BATCH * KPRE + base];
        sx2[i] = g_box[2 * BATCH * KPRE + base];
        sy2[i] = g_box[3 * BATCH * KPRE + base];
        sar[i] = g_box[4 * BATCH * KPRE + base];
    }
    __syncthreads();

    int i = blockIdx.x * 128 + tid;   // this thread's row
    float ax1 = sx1[i], ay1 = sy1[i], ax2 = sx2[i], ay2 = sy2[i], aa = sar[i];
    unsigned* dst = g_sup + ((size_t)b * KPRE + i) * 16;

    for (int wd = 0; wd < 16; wd++) {
        unsigned bits = 0u;
#pragma unroll 8
        for (int t = 0; t < 32; t++) {
            int j = wd * 32 + t;
            float ix1 = fmaxf(ax1, sx1[j]);
            float iy1 = fmaxf(ay1, sy1[j]);
            float ix2 = fminf(ax2, sx2[j]);
            float iy2 = fminf(ay2, sy2[j]);
            float iw = fmaxf(ix2 - ix1, 0.f);
            float ih = fmaxf(iy2 - iy1, 0.f);
            float inter = iw * ih;
            float uni = aa + sar[j] - inter;
            float iou = inter / (uni + 1e-9f);
            if (iou > IOU_TH) bits |= (1u << t);
        }
        dst[wd] = bits;
    }
}

// ---------------------------------------------------------------------------
// K5: kept-box-centric greedy NMS (register-resident alive mask, early exit
// at 100 kept) + emit. One block (256 threads) per batch.
// ---------------------------------------------------------------------------
__global__ void k_nms(float* __restrict__ out, int out_size) {
    __shared__ unsigned ssup[KPRE * 16];   // 32 KB
    __shared__ int skept[MAXOUT];
    __shared__ int snk;

    int b = blockIdx.x, tid = threadIdx.x;   // 256

    // stage suppression mask (L2-resident) into smem, vectorized
    {
        const uint4* src = (const uint4*)(g_sup + (size_t)b * KPRE * 16);
        uint4* dstv = (uint4*)ssup;
        for (int i = tid; i < KPRE * 16 / 4; i += 256) dstv[i] = src[i];
    }
    __syncthreads();

    if (tid < 32) {
        int lane = tid;
        unsigned alive = (lane < 16) ? g_valid[b * 16 + lane] : 0u;
        int nk = 0;
        while (nk < MAXOUT) {
            unsigned bal = __ballot_sync(FULLM, alive != 0u);
            if (!bal) break;
            int tl = __ffs(bal) - 1;                       // first lane with alive bits
            unsigned w = __shfl_sync(FULLM, alive, tl);
            int bit = __ffs(w) - 1;
            int i = (tl << 5) + bit;                       // first alive index = next kept
            if (lane == 0) skept[nk] = i;
            nk++;
            unsigned sup = (lane < 16) ? ssup[i * 16 + lane] : 0u;
            alive &= ~sup;                                 // suppress overlapping later boxes
            if (lane == tl) alive &= ~(1u << bit);         // self (iou=1 also covers this)
        }
        if (lane == 0) snk = nk;
    }
    __syncthreads();

    int nk = snk;
    float* dets = out + (size_t)b * MAXOUT * 7;
    bool has_mask = (out_size >= BATCH * MAXOUT * 7 + BATCH * MAXOUT);
    float* mask = out + (size_t)BATCH * MAXOUT * 7 + (size_t)b * MAXOUT;

    for (int r = tid; r < MAXOUT; r += 256) {
        if (r < nk) {
            int i = skept[r];
            const float* d = g_det + ((size_t)b * KPRE + i) * 7;
            float* o = dets + (size_t)r * 7;
#pragma unroll
            for (int c = 0; c < 7; c++) o[c] = d[c];
            if (has_mask) mask[r] = 1.0f;
        } else {
            float* o = dets + (size_t)r * 7;
#pragma unroll
            for (int c = 0; c < 7; c++) o[c] = 0.f;
            if (has_mask) mask[r] = 0.f;
        }
    }
}

// ---------------------------------------------------------------------------
extern "C" void kernel_launch(void* const* d_in, const int* in_sizes, int n_in,
                              void* d_out, int out_size) {
    (void)in_sizes; (void)n_in;
    const float* pred = (const float*)d_in[0];
    float* out = (float*)d_out;

    static_assert(NPRED % 8 == 0, "rows per block");
    static_assert(BATCH * 16 <= 512, "init coverage");

    cudaFuncSetAttribute(k_select, cudaFuncAttributeMaxDynamicSharedMemorySize,
                         (NPRED + KPRE) * 8);

    k_init<<<1, 512>>>();
    dim3 gs(NPRED / 8, BATCH);
    k_score<<<gs, 256>>>(pred);
    k_select<<<BATCH, 1024, (NPRED + KPRE) * 8>>>();
    dim3 gg(KPRE / 8, BATCH);
    k_gather<<<gg, 256>>>(pred);
    dim3 gi(KPRE / 128, BATCH);
    k_iou<<<gi, 128>>>();
    k_nms<<<BATCH, 256>>>(out, out_size);
}

// round 11
// speedup vs baseline: 3.1200x; 1.6241x over previous
#include <cuda_runtime.h>
#include <cstdint>

#define BATCH   32
#define NPRED   8400
#define NCLS    80
#define ROWF    85
#define KPRE    512
#define MAXOUT  100
#define RPB     24          // rows per k_score block: 24*85*4 = 8160 B = 510 float4
#define CONF_TH 0.25f
#define IOU_TH  0.45f
#define CLS_OFF 4096.0f
#define FULLM   0xFFFFFFFFu

// Scratch (no allocations allowed -> device globals)
__device__ unsigned long long g_keys[BATCH * NPRED];
__device__ unsigned long long g_topk[BATCH * KPRE];
__device__ float              g_box[5 * BATCH * KPRE];   // SoA: x1,y1,x2,y2,area (class-offset applied)
__device__ float              g_det[BATCH * KPRE * 7];   // x1,y1,x2,y2,obj,conf,cls
__device__ unsigned char     g_validb[BATCH * KPRE];
__device__ unsigned int       g_sup[BATCH * KPRE * 16];  // 1 MB suppression bitmask

// ---------------------------------------------------------------------------
// K1: streaming score pass. Block stages 24 rows (510 aligned float4) into
// smem with fully-coalesced LDG.128, then warp-per-row max-reduce.
// key = (score_bits<<32) | ~n  (unique). No atomics, no bmax (moved to K2).
// ---------------------------------------------------------------------------
__global__ void k_score(const float* __restrict__ pred) {
    __shared__ float srow[RPB * ROWF];     // 8160 B
    int tid = threadIdx.x;                 // 384
    int warp = tid >> 5, lane = tid & 31;  // 12 warps
    int b = blockIdx.y;
    int row0 = blockIdx.x * RPB;

    // base element index is a multiple of 4 (RPB*ROWF = 2040, NPRED*ROWF = 714000)
    const float4* src = (const float4*)(pred + ((size_t)b * NPRED + row0) * ROWF);
    float4* dst4 = (float4*)srow;
    for (int i = tid; i < RPB * ROWF / 4; i += 384) dst4[i] = src[i];
    __syncthreads();

#pragma unroll
    for (int rr = 0; rr < 2; rr++) {
        int r = warp * 2 + rr;             // 0..23
        const float* row = srow + r * ROWF;
        float best = -1.f;
#pragma unroll
        for (int i = 0; i < 3; i++) {
            int c = lane + i * 32;
            float v = (c < NCLS) ? row[5 + c] : -1.f;
            best = fmaxf(best, v);
        }
#pragma unroll
        for (int off = 16; off; off >>= 1)
            best = fmaxf(best, __shfl_xor_sync(FULLM, best, off));
        if (lane == 0) {
            float score = row[4] * best;              // >= 0
            unsigned sb = __float_as_uint(score);     // positive-float bit order == int order
            int n = row0 + r;
            g_keys[(size_t)b * NPRED + n] =
                ((unsigned long long)sb << 32) | (unsigned)(~(unsigned)n);
        }
    }
}

// ---------------------------------------------------------------------------
// K2: per-batch conf (= min(0.25, max score)) + exact top-512 radix-select on
// unique 64-bit keys + bitonic sort descending. One 512-thread block / batch.
// ---------------------------------------------------------------------------
__global__ void k_select() {
    extern __shared__ unsigned long long s_keys[];   // NPRED + KPRE entries
    unsigned long long* topsm = s_keys + NPRED;

    __shared__ unsigned int        hist[256];
    __shared__ unsigned int        wmax[16];
    __shared__ unsigned int        sh_confb;
    __shared__ unsigned long long  sh_prefix;
    __shared__ int                 sh_remaining;
    __shared__ unsigned int        cnt;

    int b = blockIdx.x;
    int tid = threadIdx.x;                 // 512
    int warp = tid >> 5, lane = tid & 31;  // 16 warps
    const int NITER = (NPRED + 511) / 512; // uniform trip count (17)

    // load keys + running max of score field
    unsigned mymax = 0u;
    for (int i = tid; i < NPRED; i += 512) {
        unsigned long long k = g_keys[(size_t)b * NPRED + i];
        s_keys[i] = k;
        unsigned sb = (unsigned)(k >> 32);
        mymax = mymax > sb ? mymax : sb;
    }
#pragma unroll
    for (int off = 16; off; off >>= 1) {
        unsigned v = __shfl_xor_sync(FULLM, mymax, off);
        mymax = mymax > v ? mymax : v;
    }
    if (lane == 0) wmax[warp] = mymax;
    __syncthreads();
    if (tid < 32) {
        unsigned v = (lane < 16) ? wmax[lane] : 0u;
#pragma unroll
        for (int off = 16; off; off >>= 1) {
            unsigned o = __shfl_xor_sync(FULLM, v, off);
            v = v > o ? v : o;
        }
        if (lane == 0) {
            float conf = fminf(CONF_TH, __uint_as_float(v));
            sh_confb = __float_as_uint(conf);
            sh_prefix = 0ull;
            sh_remaining = KPRE;
        }
    }
    __syncthreads();
    unsigned confb = sh_confb;

    // mask invalid (score < conf) -> score field 0 (acts as -inf; index kept)
    for (int i = tid; i < NPRED; i += 512) {
        unsigned long long k = s_keys[i];
        if ((unsigned)(k >> 32) < confb) s_keys[i] = k & 0xFFFFFFFFull;
    }
    __syncthreads();

    // 8x 8-bit radix select: find exact KPRE-th largest key
    for (int p = 7; p >= 0; p--) {
        if (tid < 256) hist[tid] = 0u;
        __syncthreads();
        unsigned long long pref = sh_prefix;
        // uniform trip count: every lane executes __match_any every iteration
        for (int it = 0; it < NITER; it++) {
            int i = it * 512 + tid;
            unsigned bucket = 0x100u;      // sentinel: inactive / non-matching
            if (i < NPRED) {
                unsigned long long k = s_keys[i];
                bool match = (p == 7) || ((k >> ((p + 1) * 8)) == pref);
                if (match) bucket = (unsigned)(k >> (p * 8)) & 0xFFu;
            }
            unsigned peers = __match_any_sync(FULLM, bucket);
            if (bucket != 0x100u && ((__ffs(peers) - 1) == lane))
                atomicAdd(&hist[bucket], __popc(peers));
        }
        __syncthreads();
        if (tid < 32) {
            int rem = sh_remaining;
            unsigned s = 0;
#pragma unroll
            for (int q = 0; q < 8; q++) s += hist[(lane << 3) + q];
            unsigned S = s;                // inclusive suffix sum across lanes
#pragma unroll
            for (int off = 1; off < 32; off <<= 1) {
                unsigned v = __shfl_down_sync(FULLM, S, off);
                if (lane + off < 32) S += v;
            }
            unsigned bal = __ballot_sync(FULLM, (int)S >= rem);
            int L = 31 - __clz(bal);       // highest lane group reaching rem
            if (lane == L) {
                int cum = (int)(S - s);    // suffix excluding this group
                for (int bb = (L << 3) + 7; bb >= (L << 3); bb--) {
                    cum += (int)hist[bb];
                    if (cum >= rem) {
                        sh_remaining = rem - (cum - (int)hist[bb]);
                        sh_prefix = (pref << 8) | (unsigned)bb;
                        break;
                    }
                }
            }
        }
        __syncthreads();
    }

    unsigned long long pivot = sh_prefix;   // exact 512th-largest key
    if (tid == 0) cnt = 0u;
    __syncthreads();

    // compact: keys unique -> exactly KPRE keys >= pivot
    for (int i = tid; i < NPRED; i += 512) {
        unsigned long long k = s_keys[i];
        if (k >= pivot) {
            unsigned pos = atomicAdd(&cnt, 1u);
            topsm[pos] = k;
        }
    }
    __syncthreads();

    // bitonic sort descending (512 elems, 512 threads)
    for (int kk = 2; kk <= KPRE; kk <<= 1) {
        for (int j = kk >> 1; j > 0; j >>= 1) {
            int ixj = tid ^ j;
            if (ixj > tid) {
                bool up = ((tid & kk) == 0);
                unsigned long long a = topsm[tid], c = topsm[ixj];
                bool sw = up ? (a < c) : (a > c);
                if (sw) { topsm[tid] = c; topsm[ixj] = a; }
            }
            __syncthreads();
        }
    }

    for (int i = tid; i < KPRE; i += 512)
        g_topk[(size_t)b * KPRE + i] = topsm[i];
}

// ---------------------------------------------------------------------------
// K3: gather selected rows -> boxes (class-offset) + dets + valid bytes.
// Grid (64, BATCH) x 256 threads, one warp per entry: latency fully hidden.
// ---------------------------------------------------------------------------
__global__ void k_gather(const float* __restrict__ pred) {
    int warp = threadIdx.x >> 5, lane = threadIdx.x & 31;
    int b = blockIdx.y;
    int e = blockIdx.x * 8 + warp;

    unsigned long long key = g_topk[(size_t)b * KPRE + e];
    unsigned sb = (unsigned)(key >> 32);
    int n = (int)(~(unsigned)key);
    const float* row = pred + ((size_t)b * NPRED + n) * ROWF;

    float bv = -1.f; int bi = 0;
#pragma unroll
    for (int i = 0; i < 3; i++) {
        int c = lane + i * 32;
        if (c < NCLS) {
            float v = row[5 + c];
            if (v > bv) { bv = v; bi = c; }
        }
    }
#pragma unroll
    for (int off = 16; off; off >>= 1) {
        float ov = __shfl_xor_sync(FULLM, bv, off);
        int   oi = __shfl_xor_sync(FULLM, bi, off);
        if (ov > bv || (ov == bv && oi < bi)) { bv = ov; bi = oi; }
    }
    if (lane == 0) {
        float cx = row[0], cy = row[1], w = row[2], h = row[3], obj = row[4];
        float x1 = cx - 0.5f * w, y1 = cy - 0.5f * h;
        float x2 = cx + 0.5f * w, y2 = cy + 0.5f * h;
        float off = (float)bi * CLS_OFF;
        int base = b * KPRE + e;
        g_box[0 * BATCH * KPRE + base] = x1 + off;
        g_box[1 * BATCH * KPRE + base] = y1 + off;
        g_box[2 * BATCH * KPRE + base] = x2 + off;
        g_box[3 * BATCH * KPRE + base] = y2 + off;
        g_box[4 * BATCH * KPRE + base] = (x2 - x1) * (y2 - y1);
        float* d = g_det + (size_t)base * 7;
        d[0] = x1; d[1] = y1; d[2] = x2; d[3] = y2;
        d[4] = obj; d[5] = bv; d[6] = (float)bi;
        g_validb[base] = (sb != 0u) ? 1 : 0;   // unconditional -> no init kernel
    }
}

// ---------------------------------------------------------------------------
// K4: suppression bitmask sup[i] bit j <=> iou(i,j) > thresh.
// Grid (32, BATCH) x 512 threads: one warp per row i, ballot forms each word.
// ---------------------------------------------------------------------------
__global__ void k_iou() {
    __shared__ float sx1[KPRE], sy1[KPRE], sx2[KPRE], sy2[KPRE], sar[KPRE];
    int b = blockIdx.y;
    int tid = threadIdx.x;                 // 512
    int warp = tid >> 5, lane = tid & 31;  // 16 warps

    {
        int base = b * KPRE + tid;
        sx1[tid] = g_box[0 * BATCH * KPRE + base];
        sy1[tid] = g_box[1 * BATCH * KPRE + base];
        sx2[tid] = g_box[2 * BATCH * KPRE + base];
        sy2[tid] = g_box[3 * BATCH * KPRE + base];
        sar[tid] = g_box[4 * BATCH * KPRE + base];
    }
    __syncthreads();

    int i = blockIdx.x * 16 + warp;        // this warp's row
    float ax1 = sx1[i], ay1 = sy1[i], ax2 = sx2[i], ay2 = sy2[i], aa = sar[i];
    unsigned* dst = g_sup + ((size_t)b * KPRE + i) * 16;

#pragma unroll
    for (int wd = 0; wd < 16; wd++) {
        int j = (wd << 5) + lane;
        float ix1 = fmaxf(ax1, sx1[j]);
        float iy1 = fmaxf(ay1, sy1[j]);
        float ix2 = fminf(ax2, sx2[j]);
        float iy2 = fminf(ay2, sy2[j]);
        float iw = fmaxf(ix2 - ix1, 0.f);
        float ih = fmaxf(iy2 - iy1, 0.f);
        float inter = iw * ih;
        float uni = aa + sar[j] - inter;
        float iou = inter / (uni + 1e-9f);
        unsigned bits = __ballot_sync(FULLM, iou > IOU_TH);
        if (lane == 0) dst[wd] = bits;
    }
}

// ---------------------------------------------------------------------------
// K5: kept-box-centric greedy NMS (register-resident alive mask, early exit
// at 100 kept) + emit. One block (256 threads) per batch.
// ---------------------------------------------------------------------------
__global__ void k_nms(float* __restrict__ out, int out_size) {
    __shared__ unsigned ssup[KPRE * 16];   // 32 KB
    __shared__ unsigned svalid[16];
    __shared__ int skept[MAXOUT];
    __shared__ int snk;

    int b = blockIdx.x, tid = threadIdx.x;   // 256

    // stage suppression mask (L2-resident) into smem, vectorized
    {
        const uint4* src = (const uint4*)(g_sup + (size_t)b * KPRE * 16);
        uint4* dstv = (uint4*)ssup;
        for (int i = tid; i < KPRE * 16 / 4; i += 256) dstv[i] = src[i];
    }
    // build valid bitmask from bytes (uniform full-warp ballots)
#pragma unroll
    for (int r = 0; r < 2; r++) {
        int idx = r * 256 + tid;
        bool v = g_validb[b * KPRE + idx] != 0;
        unsigned w = __ballot_sync(FULLM, v);
        if ((tid & 31) == 0) svalid[idx >> 5] = w;
    }
    __syncthreads();

    if (tid < 32) {
        int lane = tid;
        unsigned alive = (lane < 16) ? svalid[lane] : 0u;
        int nk = 0;
        while (nk < MAXOUT) {
            unsigned bal = __ballot_sync(FULLM, alive != 0u);
            if (!bal) break;
            int tl = __ffs(bal) - 1;                       // first lane with alive bits
            unsigned w = __shfl_sync(FULLM, alive, tl);
            int bit = __ffs(w) - 1;
            int i = (tl << 5) + bit;                       // first alive index = next kept
            if (lane == 0) skept[nk] = i;
            nk++;
            unsigned sup = (lane < 16) ? ssup[i * 16 + lane] : 0u;
            alive &= ~sup;                                 // suppress overlapping later boxes
            if (lane == tl) alive &= ~(1u << bit);         // self
        }
        if (lane == 0) snk = nk;
    }
    __syncthreads();

    int nk = snk;
    float* dets = out + (size_t)b * MAXOUT * 7;
    bool has_mask = (out_size >= BATCH * MAXOUT * 7 + BATCH * MAXOUT);
    float* mask = out + (size_t)BATCH * MAXOUT * 7 + (size_t)b * MAXOUT;

    for (int r = tid; r < MAXOUT; r += 256) {
        if (r < nk) {
            int i = skept[r];
            const float* d = g_det + ((size_t)b * KPRE + i) * 7;
            float* o = dets + (size_t)r * 7;
#pragma unroll
            for (int c = 0; c < 7; c++) o[c] = d[c];
            if (has_mask) mask[r] = 1.0f;
        } else {
            float* o = dets + (size_t)r * 7;
#pragma unroll
            for (int c = 0; c < 7; c++) o[c] = 0.f;
            if (has_mask) mask[r] = 0.f;
        }
    }
}

// ---------------------------------------------------------------------------
extern "C" void kernel_launch(void* const* d_in, const int* in_sizes, int n_in,
                              void* d_out, int out_size) {
    (void)in_sizes; (void)n_in;
    const float* pred = (const float*)d_in[0];
    float* out = (float*)d_out;

    static_assert(NPRED % RPB == 0, "rows per block");
    static_assert((RPB * ROWF) % 4 == 0, "float4 staging");
    static_assert((NPRED * ROWF) % 4 == 0, "float4 batch base");

    cudaFuncSetAttribute(k_select, cudaFuncAttributeMaxDynamicSharedMemorySize,
                         (NPRED + KPRE) * 8);

    dim3 gs(NPRED / RPB, BATCH);           // (350, 32)
    k_score<<<gs, 384>>>(pred);
    k_select<<<BATCH, 512, (NPRED + KPRE) * 8>>>();
    dim3 gg(KPRE / 8, BATCH);              // (64, 32)
    k_gather<<<gg, 256>>>(pred);
    dim3 gi(KPRE / 16, BATCH);             // (32, 32)
    k_iou<<<gi, 512>>>();
    k_nms<<<BATCH, 256>>>(out, out_size);
}